// round 16
// baseline (speedup 1.0000x reference)
#include <cuda_runtime.h>
#include <cuda_fp16.h>
#include <math.h>
#include <stdint.h>

#define BB 4
#define SS 4096
#define HH 128
#define ROWS_TOTAL (BB * SS)

// Scratch (allocation-free path). Q pre-scaled by log2(e)/sqrt(H). All fp16.
// V stored transposed: g_Vt[b][h][s].
__device__ __half g_Q[ROWS_TOTAL * HH];
__device__ __half g_K[ROWS_TOTAL * HH];
__device__ __half g_Vt[BB * HH * SS];

__device__ __forceinline__ uint32_t hex2(uint32_t h2) {
    uint32_t y;
    asm("ex2.approx.f16x2 %0, %1;" : "=r"(y) : "r"(h2));
    return y;
}

__device__ __forceinline__ uint32_t smem_u32_of(const void* p) {
    uint32_t a;
    asm("{ .reg .u64 t; cvta.to.shared.u64 t, %1; cvt.u32.u64 %0, t; }" : "=r"(a) : "l"(p));
    return a;
}

__device__ __forceinline__ void cp_async16(uint32_t dst, const void* src) {
    asm volatile("cp.async.cg.shared.global [%0], [%1], 16;" :: "r"(dst), "l"(src));
}
#define CP_COMMIT() asm volatile("cp.async.commit_group;" ::: "memory")
#define CP_WAIT0()  asm volatile("cp.async.wait_group 0;" ::: "memory")

__device__ __forceinline__ void ldsm_x4(uint32_t* r, uint32_t addr) {
    asm volatile("ldmatrix.sync.aligned.m8n8.x4.shared.b16 {%0,%1,%2,%3}, [%4];"
        : "=r"(r[0]), "=r"(r[1]), "=r"(r[2]), "=r"(r[3]) : "r"(addr));
}

// fp16 m16n8k16 with fp32 accumulate (validated R9-R15)
__device__ __forceinline__ void mma_f16(float* d, const uint32_t* a,
                                        uint32_t b0, uint32_t b1) {
    asm volatile(
        "mma.sync.aligned.m16n8k16.row.col.f32.f16.f16.f32 "
        "{%0,%1,%2,%3}, {%4,%5,%6,%7}, {%8,%9}, {%0,%1,%2,%3};"
        : "+f"(d[0]), "+f"(d[1]), "+f"(d[2]), "+f"(d[3])
        : "r"(a[0]), "r"(a[1]), "r"(a[2]), "r"(a[3]), "r"(b0), "r"(b1));
}

// fp16 m16n8k16 with fp16 accumulate (full rate; validated R14 for S GEMM)
__device__ __forceinline__ void mma_f16h(uint32_t* d, const uint32_t* a,
                                         uint32_t b0, uint32_t b1) {
    asm volatile(
        "mma.sync.aligned.m16n8k16.row.col.f16.f16.f16.f16 "
        "{%0,%1}, {%2,%3,%4,%5}, {%6,%7}, {%0,%1};"
        : "+r"(d[0]), "+r"(d[1])
        : "r"(a[0]), "r"(a[1]), "r"(a[2]), "r"(a[3]), "r"(b0), "r"(b1));
}

#define ONES_H2 0x3C003C00u

// ---------------------------------------------------------------------------
// Kernel 1: QKV projection, single wave (validated R14). Grid 128, 256 thr.
// chunk 0 -> Q (scaled by log2e/sqrt(H)), 1 -> K, 2 -> V^T (via St overlay).
// V^T gmem stores vectorized as half2 (2 consecutive s per thread).
// ---------------------------------------------------------------------------
#define QS_X 0
#define QS_W 8192
#define QS_BIAS 32768
#define SMEM_QKV ((32768 + 384) * 4)   // 132608 B

__global__ __launch_bounds__(256, 1) void qkv_f16(const float* __restrict__ X,
                                                  const float* __restrict__ W,
                                                  const float* __restrict__ bias)
{
    extern __shared__ uint32_t smu[];
    const uint32_t smem_u32 = smem_u32_of(smu);
    float* Bs = (float*)(smu + QS_BIAS);

    const int tid = threadIdx.x;
    const int wid = tid >> 5;
    const int lane = tid & 31;
    const int g = lane >> 2;
    const int tg = lane & 3;
    const int m0 = (wid >> 1) * 32;
    const int n0 = (wid & 1) * 64;
    const int row0 = blockIdx.x * 128;

    const int j = lane & 7;
    const int mat = lane >> 3;
    const uint32_t xhi4 = (uint32_t)((4 * j) & 24) << 2;
    const int rowA = j + 8 * (mat & 1);
    const uint32_t xloA = 16u * (((mat >> 1) ^ j) & 1);
    const int rowB = j + 8 * (mat >> 1);
    const uint32_t xloB = 16u * (((mat & 1) ^ j) & 1);

    const uint32_t xBase = smem_u32 + QS_X * 4 + (uint32_t)(m0 + rowA) * 256 + xloA;
    const uint32_t wBase0 = smem_u32 + QS_W * 4 + (uint32_t)(n0 + rowB) * 256 + xloB;

    {
        const float4* Xg = (const float4*)(X + (size_t)row0 * HH);
        #pragma unroll
        for (int i = 0; i < 16; i++) {
            int idx = tid + i * 256;
            int r = idx >> 5;
            int uc = (idx & 31) << 1;
            int sw = uc ^ ((r & 7) << 2);
            float4 v = Xg[idx];
            __half2 h01 = __floats2half2_rn(v.x, v.y);
            __half2 h23 = __floats2half2_rn(v.z, v.w);
            uint2 u;
            u.x = *reinterpret_cast<uint32_t*>(&h01);
            u.y = *reinterpret_cast<uint32_t*>(&h23);
            *(uint2*)(smu + QS_X + r * 64 + sw) = u;
        }
        const float4* Wg = (const float4*)W;
        #pragma unroll
        for (int i = 0; i < 48; i++) {
            int idx = tid + i * 256;
            int r = idx >> 5;
            int uc = (idx & 31) << 1;
            int sw = uc ^ ((r & 7) << 2);
            float4 w = Wg[idx];
            __half2 w01 = __floats2half2_rn(w.x, w.y);
            __half2 w23 = __floats2half2_rn(w.z, w.w);
            uint2 uw;
            uw.x = *reinterpret_cast<uint32_t*>(&w01);
            uw.y = *reinterpret_cast<uint32_t*>(&w23);
            *(uint2*)(smu + QS_W + (r >> 7) * 8192 + (r & 127) * 64 + sw) = uw;
        }
        Bs[tid] = bias[tid];
        if (tid < 128) Bs[256 + tid] = bias[256 + tid];
    }
    __syncthreads();

    #pragma unroll 1
    for (int c = 0; c < 3; c++) {
        const uint32_t wBase = wBase0 + (uint32_t)c * 32768u;
        const float* Bc = Bs + c * 128;

        float acc[2][8][4];
        #pragma unroll
        for (int st = 0; st < 2; st++)
            #pragma unroll
            for (int nt = 0; nt < 8; nt++)
                #pragma unroll
                for (int jj = 0; jj < 4; jj++) acc[st][nt][jj] = 0.0f;

        #pragma unroll
        for (int ks = 0; ks < 8; ks++) {
            const uint32_t col4 = ((uint32_t)(ks * 32)) ^ xhi4;
            uint32_t a0[4], a1[4];
            ldsm_x4(a0, xBase + col4);
            ldsm_x4(a1, xBase + col4 + 4096);
            #pragma unroll
            for (int nb = 0; nb < 4; nb++) {
                uint32_t bw[4];
                ldsm_x4(bw, wBase + (uint32_t)nb * 4096 + col4);
                mma_f16(acc[0][2 * nb],     a0, bw[0], bw[1]);
                mma_f16(acc[1][2 * nb],     a1, bw[0], bw[1]);
                mma_f16(acc[0][2 * nb + 1], a0, bw[2], bw[3]);
                mma_f16(acc[1][2 * nb + 1], a1, bw[2], bw[3]);
            }
        }

        if (c == 2) {
            __syncthreads();
            float* St = (float*)smu;    // 128 x 130 (s rows, h cols)
            #pragma unroll
            for (int st = 0; st < 2; st++) {
                #pragma unroll
                for (int nt = 0; nt < 8; nt++) {
                    int col = n0 + nt * 8 + 2 * tg;
                    int r0 = m0 + 16 * st + g;
                    int r1 = r0 + 8;
                    float b0v = Bc[col], b1v = Bc[col + 1];
                    *(float2*)(St + r0 * 130 + col) =
                        make_float2(acc[st][nt][0] + b0v, acc[st][nt][1] + b1v);
                    *(float2*)(St + r1 * 130 + col) =
                        make_float2(acc[st][nt][2] + b0v, acc[st][nt][3] + b1v);
                }
            }
            __syncthreads();
            const int b = row0 >> 12;
            const int sbase = row0 & 4095;
            const float* Stc = (const float*)smu;
            #pragma unroll 4
            for (int i = 0; i < 32; i++) {
                int idx = tid + i * 256;
                int h = idx >> 6;
                int s2 = (idx & 63) << 1;
                __half2 hv = __floats2half2_rn(Stc[s2 * 130 + h],
                                               Stc[(s2 + 1) * 130 + h]);
                *(__half2*)(g_Vt + ((size_t)(b * HH + h)) * SS + sbase + s2) = hv;
            }
        } else {
            __half* dst = (c == 0 ? g_Q : g_K) + (size_t)row0 * HH;
            const float scale = (c == 0)
                ? (0.08838834764831845f * 1.4426950408889634f) : 1.0f;
            #pragma unroll
            for (int st = 0; st < 2; st++) {
                #pragma unroll
                for (int nt = 0; nt < 8; nt++) {
                    int col = n0 + nt * 8 + 2 * tg;
                    int r0 = m0 + 16 * st + g;
                    int r1 = r0 + 8;
                    float b0v = Bc[col], b1v = Bc[col + 1];
                    *(__half2*)(dst + (size_t)r0 * HH + col) =
                        __floats2half2_rn((acc[st][nt][0] + b0v) * scale,
                                          (acc[st][nt][1] + b1v) * scale);
                    *(__half2*)(dst + (size_t)r1 * HH + col) =
                        __floats2half2_rn((acc[st][nt][2] + b0v) * scale,
                                          (acc[st][nt][3] + b1v) * scale);
                }
            }
        }
    }
}

// ---------------------------------------------------------------------------
// Kernel 2: flash attention — R14 mainloop exactly (register P, ones-MMA
// lsum, fp16-acc S GEMM). NEW: balanced epilogue — each warp publishes the
// 64 head-cols it does NOT own + its lsum; after one sync each warp combines
// and writes its own 64 cols. 256 threads, 8 warps = 4 m-strips x 2 kh.
// SMEM u32: Q[8192] K0 K1 V0 V1 = 160KB. Swizzle u32col^4*(row&7).
// ---------------------------------------------------------------------------
#define UQ  0
#define UK0 8192
#define UV0 24576
#define ULS0 16384           // lsum of kh=0 warps (128 f32), post-loop overlay
#define ULS1 16512           // lsum of kh=1 warps
#define SMEM_ATTN (40960 * 4)   // 163840 B

__global__ __launch_bounds__(256, 1) void attn_kernel(float* __restrict__ out)
{
    extern __shared__ uint32_t smu[];
    const uint32_t smem_u32 = smem_u32_of(smu);

    const int tid = threadIdx.x;
    const int wid = tid >> 5;
    const int lane = tid & 31;
    const int g = lane >> 2;
    const int tg = lane & 3;
    const int m0 = (wid >> 1) * 32;   // m-strip
    const int kh = wid & 1;           // key-half
    const int b = blockIdx.y;
    const int q0 = blockIdx.x * 128;

    const int j = lane & 7;
    const int mat = lane >> 3;
    const uint32_t xhi4 = (uint32_t)((4 * j) & 24) << 2;
    const int rowA = j + 8 * (mat & 1);
    const uint32_t xloA = 16u * (((mat >> 1) ^ j) & 1);
    const int rowB = j + 8 * (mat >> 1);
    const uint32_t xloB = 16u * (((mat & 1) ^ j) & 1);

    const uint32_t qBase   = smem_u32 + UQ * 4 + (uint32_t)(m0 + rowA) * 256 + xloA;
    const uint32_t kCommon = smem_u32 + UK0 * 4 + (uint32_t)(kh * 64 + rowB) * 256 + xloB;
    const uint32_t vCommon = smem_u32 + UV0 * 4 + (uint32_t)rowB * 256 + xloB;
    const uint32_t vColOff = (uint32_t)(kh * 128);

    // ---- prologue: stage tile 0 (K,V) + Q ----
    {
        const __half* Kg = g_K + ((size_t)b * SS) * HH;
        const __half* Vg = g_Vt + (size_t)(b * HH) * SS;
        #pragma unroll
        for (int i = 0; i < 8; i++) {
            int idx = tid + i * 256;
            int r = idx >> 4;
            int c4 = (idx & 15) << 2;
            int sw = c4 ^ ((r & 7) << 2);
            cp_async16(smem_u32 + (UK0 + r * 64 + sw) * 4, Kg + r * HH + c4 * 2);
            cp_async16(smem_u32 + (UV0 + r * 64 + sw) * 4, Vg + (size_t)r * SS + c4 * 2);
        }
        CP_COMMIT();
        const __half* Qg = g_Q + ((size_t)b * SS + q0) * HH;
        #pragma unroll
        for (int i = 0; i < 8; i++) {
            int idx = tid + i * 256;
            int r = idx >> 4;
            int c4 = (idx & 15) << 2;
            int sw = c4 ^ ((r & 7) << 2);
            *(uint4*)(smu + UQ + r * 64 + sw) = *(const uint4*)(Qg + r * HH + c4 * 2);
        }
    }

    float oacc[2][16][4];
    #pragma unroll
    for (int st = 0; st < 2; st++)
        #pragma unroll
        for (int nt = 0; nt < 16; nt++)
            #pragma unroll
            for (int jj = 0; jj < 4; jj++) oacc[st][nt][jj] = 0.0f;
    float lacc[2][4];
    #pragma unroll
    for (int st = 0; st < 2; st++)
        #pragma unroll
        for (int jj = 0; jj < 4; jj++) lacc[st][jj] = 0.0f;

    for (int t = 0; t < 32; t++) {
        const uint32_t kBase = kCommon + (uint32_t)(t & 1) * 32768u;
        const uint32_t vBase = vCommon + (uint32_t)(t & 1) * 32768u;

        CP_WAIT0();
        __syncthreads();   // K(t),V(t) visible; prior reads of reused bufs done

        // Prefetch tile t+1
        if (t + 1 < 32) {
            const int ok = UK0 + ((t + 1) & 1) * 8192;
            const int ov = UV0 + ((t + 1) & 1) * 8192;
            const __half* Kg = g_K + ((size_t)b * SS + (t + 1) * 128) * HH;
            const __half* Vg = g_Vt + (size_t)(b * HH) * SS + (t + 1) * 128;
            #pragma unroll
            for (int i = 0; i < 8; i++) {
                int idx = tid + i * 256;
                int r = idx >> 4;
                int c4 = (idx & 15) << 2;
                int sw = c4 ^ ((r & 7) << 2);
                cp_async16(smem_u32 + (ok + r * 64 + sw) * 4, Kg + r * HH + c4 * 2);
                cp_async16(smem_u32 + (ov + r * 64 + sw) * 4, Vg + (size_t)r * SS + c4 * 2);
            }
            CP_COMMIT();
        }

        // --- S = Q . K^T : m32 x n64 x k128, fp16 ACCUMULATE (full rate) ---
        uint32_t sacc[2][8][2];
        #pragma unroll
        for (int st = 0; st < 2; st++)
            #pragma unroll
            for (int nt = 0; nt < 8; nt++) {
                sacc[st][nt][0] = 0u;
                sacc[st][nt][1] = 0u;
            }

        #pragma unroll
        for (int ks = 0; ks < 8; ks++) {
            const uint32_t col4 = ((uint32_t)(ks * 32)) ^ xhi4;
            uint32_t qa0[4], qa1[4];
            ldsm_x4(qa0, qBase + col4);
            ldsm_x4(qa1, qBase + col4 + 4096);
            #pragma unroll
            for (int nb = 0; nb < 4; nb++) {
                uint32_t bk[4];
                ldsm_x4(bk, kBase + (uint32_t)nb * 4096 + col4);
                mma_f16h(sacc[0][2 * nb],     qa0, bk[0], bk[1]);
                mma_f16h(sacc[1][2 * nb],     qa1, bk[0], bk[1]);
                mma_f16h(sacc[0][2 * nb + 1], qa0, bk[2], bk[3]);
                mma_f16h(sacc[1][2 * nb + 1], qa1, bk[2], bk[3]);
            }
        }

        // --- softmax: f16 C-frag -> ex2.approx.f16x2 directly ---
        uint32_t pf[4][2][4];
        #pragma unroll
        for (int st = 0; st < 2; st++) {
            #pragma unroll
            for (int nt = 0; nt < 8; nt++) {
                pf[nt >> 1][st][(nt & 1) * 2]     = hex2(sacc[st][nt][0]);
                pf[nt >> 1][st][(nt & 1) * 2 + 1] = hex2(sacc[st][nt][1]);
            }
        }

        // --- O += P . V (m32 x h128 x k64) and lsum += P . 1 (f32 acc) ---
        #pragma unroll
        for (int kk = 0; kk < 4; kk++) {
            const uint32_t col4v = (vColOff + (uint32_t)(kk * 32)) ^ xhi4;
            mma_f16(lacc[0], pf[kk][0], ONES_H2, ONES_H2);
            mma_f16(lacc[1], pf[kk][1], ONES_H2, ONES_H2);
            #pragma unroll
            for (int hb = 0; hb < 8; hb++) {
                uint32_t bv[4];
                ldsm_x4(bv, vBase + (uint32_t)hb * 4096 + col4v);
                mma_f16(oacc[0][2 * hb],     pf[kk][0], bv[0], bv[1]);
                mma_f16(oacc[1][2 * hb],     pf[kk][1], bv[0], bv[1]);
                mma_f16(oacc[0][2 * hb + 1], pf[kk][0], bv[2], bv[3]);
                mma_f16(oacc[1][2 * hb + 1], pf[kk][1], bv[2], bv[3]);
            }
        }
    }

    // --- Balanced combine: each warp publishes the 64 cols it does NOT own
    //     (nt range of the opposite kh) + its lsum. ---
    __syncthreads();   // staging done with smem; safe to reuse
    {
        float* Ocmb = (float*)smu;                 // 4 strips x 32 x 128 f32
        float* LSme = (float*)(smu + (kh ? ULS1 : ULS0));
        float* Obase = Ocmb + (m0 >> 5) * 4096;
        const int ntp = (1 - kh) * 8;   // publish opposite half's nt range
        #pragma unroll
        for (int st = 0; st < 2; st++) {
            int r0 = 16 * st + g;
            int r1 = r0 + 8;
            if (tg == 0) {
                LSme[m0 + r0] = lacc[st][0];
                LSme[m0 + r1] = lacc[st][2];
            }
            #pragma unroll
            for (int nto = 0; nto < 8; nto++) {
                int nt = ntp + nto;
                int col = nt * 8 + 2 * tg;
                *(float2*)(Obase + r0 * 128 + col) =
                    make_float2(oacc[st][nt][0], oacc[st][nt][1]);
                *(float2*)(Obase + r1 * 128 + col) =
                    make_float2(oacc[st][nt][2], oacc[st][nt][3]);
            }
        }
    }
    __syncthreads();

    // --- epilogue: each warp combines + writes its OWN 64 cols ---
    {
        const float* Ocmb = (const float*)smu + (m0 >> 5) * 4096;
        const float* LSo = (const float*)(smu + (kh ? ULS0 : ULS1));
        float* og = out + ((size_t)(b * SS) + q0) * HH;
        const int ntb = kh * 8;   // own nt range
        #pragma unroll
        for (int st = 0; st < 2; st++) {
            int r0 = 16 * st + g;
            int r1 = r0 + 8;
            float inv0 = 1.0f / (lacc[st][0] + LSo[m0 + r0]);
            float inv1 = 1.0f / (lacc[st][2] + LSo[m0 + r1]);
            float* o0 = og + (size_t)(m0 + r0) * HH;
            float* o1 = og + (size_t)(m0 + r1) * HH;
            #pragma unroll
            for (int nto = 0; nto < 8; nto++) {
                int nt = ntb + nto;
                int col = nt * 8 + 2 * tg;
                float2 p0 = *(const float2*)(Ocmb + r0 * 128 + col);
                float2 p1 = *(const float2*)(Ocmb + r1 * 128 + col);
                *(float2*)(o0 + col) = make_float2((oacc[st][nt][0] + p0.x) * inv0,
                                                   (oacc[st][nt][1] + p0.y) * inv0);
                *(float2*)(o1 + col) = make_float2((oacc[st][nt][2] + p1.x) * inv1,
                                                   (oacc[st][nt][3] + p1.y) * inv1);
            }
        }
    }
}

// ---------------------------------------------------------------------------
extern "C" void kernel_launch(void* const* d_in, const int* in_sizes, int n_in,
                              void* d_out, int out_size)
{
    const float* X    = (const float*)d_in[0];   // [4,4096,128]
    const float* W    = (const float*)d_in[1];   // [384,128]
    const float* bias = (const float*)d_in[2];   // [384]
    float* out = (float*)d_out;                  // [4,4096,128]

    cudaFuncSetAttribute(qkv_f16, cudaFuncAttributeMaxDynamicSharedMemorySize, SMEM_QKV);
    cudaFuncSetAttribute(attn_kernel, cudaFuncAttributeMaxDynamicSharedMemorySize, SMEM_ATTN);

    qkv_f16<<<128, 256, SMEM_QKV>>>(X, W, bias);
    attn_kernel<<<dim3(SS / 128, BB), 256, SMEM_ATTN>>>(out);
}

// round 17
// speedup vs baseline: 3.4623x; 3.4623x over previous
#include <cuda_runtime.h>
#include <cuda_fp16.h>
#include <math.h>
#include <stdint.h>

#define BB 4
#define SS 4096
#define HH 128
#define ROWS_TOTAL (BB * SS)

// Scratch (allocation-free path). Q pre-scaled by log2(e)/sqrt(H). All fp16.
// V stored transposed: g_Vt[b][h][s].
__device__ __half g_Q[ROWS_TOTAL * HH];
__device__ __half g_K[ROWS_TOTAL * HH];
__device__ __half g_Vt[BB * HH * SS];

__device__ __forceinline__ uint32_t hex2(uint32_t h2) {
    uint32_t y;
    asm("ex2.approx.f16x2 %0, %1;" : "=r"(y) : "r"(h2));
    return y;
}

__device__ __forceinline__ uint32_t smem_u32_of(const void* p) {
    uint32_t a;
    asm("{ .reg .u64 t; cvta.to.shared.u64 t, %1; cvt.u32.u64 %0, t; }" : "=r"(a) : "l"(p));
    return a;
}

__device__ __forceinline__ void cp_async16(uint32_t dst, const void* src) {
    asm volatile("cp.async.cg.shared.global [%0], [%1], 16;" :: "r"(dst), "l"(src));
}
#define CP_COMMIT() asm volatile("cp.async.commit_group;" ::: "memory")
#define CP_WAIT0()  asm volatile("cp.async.wait_group 0;" ::: "memory")

__device__ __forceinline__ void ldsm_x4(uint32_t* r, uint32_t addr) {
    asm volatile("ldmatrix.sync.aligned.m8n8.x4.shared.b16 {%0,%1,%2,%3}, [%4];"
        : "=r"(r[0]), "=r"(r[1]), "=r"(r[2]), "=r"(r[3]) : "r"(addr));
}

// fp16 m16n8k16 with fp32 accumulate (validated R9-R15)
__device__ __forceinline__ void mma_f16(float* d, const uint32_t* a,
                                        uint32_t b0, uint32_t b1) {
    asm volatile(
        "mma.sync.aligned.m16n8k16.row.col.f32.f16.f16.f32 "
        "{%0,%1,%2,%3}, {%4,%5,%6,%7}, {%8,%9}, {%0,%1,%2,%3};"
        : "+f"(d[0]), "+f"(d[1]), "+f"(d[2]), "+f"(d[3])
        : "r"(a[0]), "r"(a[1]), "r"(a[2]), "r"(a[3]), "r"(b0), "r"(b1));
}

// fp16 m16n8k16 with fp16 accumulate (full rate; validated R14 for S GEMM)
__device__ __forceinline__ void mma_f16h(uint32_t* d, const uint32_t* a,
                                         uint32_t b0, uint32_t b1) {
    asm volatile(
        "mma.sync.aligned.m16n8k16.row.col.f16.f16.f16.f16 "
        "{%0,%1}, {%2,%3,%4,%5}, {%6,%7}, {%0,%1};"
        : "+r"(d[0]), "+r"(d[1])
        : "r"(a[0]), "r"(a[1]), "r"(a[2]), "r"(a[3]), "r"(b0), "r"(b1));
}

#define ONES_H2 0x3C003C00u

// ---------------------------------------------------------------------------
// Kernel 1: QKV projection, single wave (validated R14/R16). Grid 128, 256 thr.
// chunk 0 -> Q (scaled by log2e/sqrt(H)), 1 -> K, 2 -> V^T (via St overlay).
// V^T gmem stores vectorized as half2.
// ---------------------------------------------------------------------------
#define QS_X 0
#define QS_W 8192
#define QS_BIAS 32768
#define SMEM_QKV ((32768 + 384) * 4)   // 132608 B

__global__ __launch_bounds__(256, 1) void qkv_f16(const float* __restrict__ X,
                                                  const float* __restrict__ W,
                                                  const float* __restrict__ bias)
{
    extern __shared__ uint32_t smu[];
    const uint32_t smem_u32 = smem_u32_of(smu);
    float* Bs = (float*)(smu + QS_BIAS);

    const int tid = threadIdx.x;
    const int wid = tid >> 5;
    const int lane = tid & 31;
    const int g = lane >> 2;
    const int tg = lane & 3;
    const int m0 = (wid >> 1) * 32;
    const int n0 = (wid & 1) * 64;
    const int row0 = blockIdx.x * 128;

    const int j = lane & 7;
    const int mat = lane >> 3;
    const uint32_t xhi4 = (uint32_t)((4 * j) & 24) << 2;
    const int rowA = j + 8 * (mat & 1);
    const uint32_t xloA = 16u * (((mat >> 1) ^ j) & 1);
    const int rowB = j + 8 * (mat >> 1);
    const uint32_t xloB = 16u * (((mat & 1) ^ j) & 1);

    const uint32_t xBase = smem_u32 + QS_X * 4 + (uint32_t)(m0 + rowA) * 256 + xloA;
    const uint32_t wBase0 = smem_u32 + QS_W * 4 + (uint32_t)(n0 + rowB) * 256 + xloB;

    {
        const float4* Xg = (const float4*)(X + (size_t)row0 * HH);
        #pragma unroll
        for (int i = 0; i < 16; i++) {
            int idx = tid + i * 256;
            int r = idx >> 5;
            int uc = (idx & 31) << 1;
            int sw = uc ^ ((r & 7) << 2);
            float4 v = Xg[idx];
            __half2 h01 = __floats2half2_rn(v.x, v.y);
            __half2 h23 = __floats2half2_rn(v.z, v.w);
            uint2 u;
            u.x = *reinterpret_cast<uint32_t*>(&h01);
            u.y = *reinterpret_cast<uint32_t*>(&h23);
            *(uint2*)(smu + QS_X + r * 64 + sw) = u;
        }
        const float4* Wg = (const float4*)W;
        #pragma unroll
        for (int i = 0; i < 48; i++) {
            int idx = tid + i * 256;
            int r = idx >> 5;
            int uc = (idx & 31) << 1;
            int sw = uc ^ ((r & 7) << 2);
            float4 w = Wg[idx];
            __half2 w01 = __floats2half2_rn(w.x, w.y);
            __half2 w23 = __floats2half2_rn(w.z, w.w);
            uint2 uw;
            uw.x = *reinterpret_cast<uint32_t*>(&w01);
            uw.y = *reinterpret_cast<uint32_t*>(&w23);
            *(uint2*)(smu + QS_W + (r >> 7) * 8192 + (r & 127) * 64 + sw) = uw;
        }
        Bs[tid] = bias[tid];
        if (tid < 128) Bs[256 + tid] = bias[256 + tid];
    }
    __syncthreads();

    #pragma unroll 1
    for (int c = 0; c < 3; c++) {
        const uint32_t wBase = wBase0 + (uint32_t)c * 32768u;
        const float* Bc = Bs + c * 128;

        float acc[2][8][4];
        #pragma unroll
        for (int st = 0; st < 2; st++)
            #pragma unroll
            for (int nt = 0; nt < 8; nt++)
                #pragma unroll
                for (int jj = 0; jj < 4; jj++) acc[st][nt][jj] = 0.0f;

        #pragma unroll
        for (int ks = 0; ks < 8; ks++) {
            const uint32_t col4 = ((uint32_t)(ks * 32)) ^ xhi4;
            uint32_t a0[4], a1[4];
            ldsm_x4(a0, xBase + col4);
            ldsm_x4(a1, xBase + col4 + 4096);
            #pragma unroll
            for (int nb = 0; nb < 4; nb++) {
                uint32_t bw[4];
                ldsm_x4(bw, wBase + (uint32_t)nb * 4096 + col4);
                mma_f16(acc[0][2 * nb],     a0, bw[0], bw[1]);
                mma_f16(acc[1][2 * nb],     a1, bw[0], bw[1]);
                mma_f16(acc[0][2 * nb + 1], a0, bw[2], bw[3]);
                mma_f16(acc[1][2 * nb + 1], a1, bw[2], bw[3]);
            }
        }

        if (c == 2) {
            __syncthreads();
            float* St = (float*)smu;    // 128 x 130 (s rows, h cols)
            #pragma unroll
            for (int st = 0; st < 2; st++) {
                #pragma unroll
                for (int nt = 0; nt < 8; nt++) {
                    int col = n0 + nt * 8 + 2 * tg;
                    int r0 = m0 + 16 * st + g;
                    int r1 = r0 + 8;
                    float b0v = Bc[col], b1v = Bc[col + 1];
                    *(float2*)(St + r0 * 130 + col) =
                        make_float2(acc[st][nt][0] + b0v, acc[st][nt][1] + b1v);
                    *(float2*)(St + r1 * 130 + col) =
                        make_float2(acc[st][nt][2] + b0v, acc[st][nt][3] + b1v);
                }
            }
            __syncthreads();
            const int b = row0 >> 12;
            const int sbase = row0 & 4095;
            const float* Stc = (const float*)smu;
            #pragma unroll 4
            for (int i = 0; i < 32; i++) {
                int idx = tid + i * 256;
                int h = idx >> 6;
                int s2 = (idx & 63) << 1;
                __half2 hv = __floats2half2_rn(Stc[s2 * 130 + h],
                                               Stc[(s2 + 1) * 130 + h]);
                *(__half2*)(g_Vt + ((size_t)(b * HH + h)) * SS + sbase + s2) = hv;
            }
        } else {
            __half* dst = (c == 0 ? g_Q : g_K) + (size_t)row0 * HH;
            const float scale = (c == 0)
                ? (0.08838834764831845f * 1.4426950408889634f) : 1.0f;
            #pragma unroll
            for (int st = 0; st < 2; st++) {
                #pragma unroll
                for (int nt = 0; nt < 8; nt++) {
                    int col = n0 + nt * 8 + 2 * tg;
                    int r0 = m0 + 16 * st + g;
                    int r1 = r0 + 8;
                    float b0v = Bc[col], b1v = Bc[col + 1];
                    *(__half2*)(dst + (size_t)r0 * HH + col) =
                        __floats2half2_rn((acc[st][nt][0] + b0v) * scale,
                                          (acc[st][nt][1] + b1v) * scale);
                    *(__half2*)(dst + (size_t)r1 * HH + col) =
                        __floats2half2_rn((acc[st][nt][2] + b0v) * scale,
                                          (acc[st][nt][3] + b1v) * scale);
                }
            }
        }
    }
}

// ---------------------------------------------------------------------------
// Kernel 2: flash attention — R14 mainloop (register P, ones-MMA lsum,
// fp16-acc S GEMM). Balanced epilogue REDONE with compile-time oacc indices
// (R16's runtime `nt` index demoted oacc to local memory -> 3.5x regression).
// 256 threads, 8 warps = 4 m-strips x 2 key-halves.
// SMEM u32: Q[8192] K0 K1 V0 V1 = 160KB. Swizzle u32col^4*(row&7).
// ---------------------------------------------------------------------------
#define UQ  0
#define UK0 8192
#define UV0 24576
#define ULS0 16384           // lsum of kh=0 warps (128 f32), post-loop overlay
#define ULS1 16512           // lsum of kh=1 warps
#define SMEM_ATTN (40960 * 4)   // 163840 B

__global__ __launch_bounds__(256, 1) void attn_kernel(float* __restrict__ out)
{
    extern __shared__ uint32_t smu[];
    const uint32_t smem_u32 = smem_u32_of(smu);

    const int tid = threadIdx.x;
    const int wid = tid >> 5;
    const int lane = tid & 31;
    const int g = lane >> 2;
    const int tg = lane & 3;
    const int m0 = (wid >> 1) * 32;   // m-strip
    const int kh = wid & 1;           // key-half
    const int b = blockIdx.y;
    const int q0 = blockIdx.x * 128;

    const int j = lane & 7;
    const int mat = lane >> 3;
    const uint32_t xhi4 = (uint32_t)((4 * j) & 24) << 2;
    const int rowA = j + 8 * (mat & 1);
    const uint32_t xloA = 16u * (((mat >> 1) ^ j) & 1);
    const int rowB = j + 8 * (mat >> 1);
    const uint32_t xloB = 16u * (((mat & 1) ^ j) & 1);

    const uint32_t qBase   = smem_u32 + UQ * 4 + (uint32_t)(m0 + rowA) * 256 + xloA;
    const uint32_t kCommon = smem_u32 + UK0 * 4 + (uint32_t)(kh * 64 + rowB) * 256 + xloB;
    const uint32_t vCommon = smem_u32 + UV0 * 4 + (uint32_t)rowB * 256 + xloB;
    const uint32_t vColOff = (uint32_t)(kh * 128);

    // ---- prologue: stage tile 0 (K,V) + Q ----
    {
        const __half* Kg = g_K + ((size_t)b * SS) * HH;
        const __half* Vg = g_Vt + (size_t)(b * HH) * SS;
        #pragma unroll
        for (int i = 0; i < 8; i++) {
            int idx = tid + i * 256;
            int r = idx >> 4;
            int c4 = (idx & 15) << 2;
            int sw = c4 ^ ((r & 7) << 2);
            cp_async16(smem_u32 + (UK0 + r * 64 + sw) * 4, Kg + r * HH + c4 * 2);
            cp_async16(smem_u32 + (UV0 + r * 64 + sw) * 4, Vg + (size_t)r * SS + c4 * 2);
        }
        CP_COMMIT();
        const __half* Qg = g_Q + ((size_t)b * SS + q0) * HH;
        #pragma unroll
        for (int i = 0; i < 8; i++) {
            int idx = tid + i * 256;
            int r = idx >> 4;
            int c4 = (idx & 15) << 2;
            int sw = c4 ^ ((r & 7) << 2);
            *(uint4*)(smu + UQ + r * 64 + sw) = *(const uint4*)(Qg + r * HH + c4 * 2);
        }
    }

    float oacc[2][16][4];
    #pragma unroll
    for (int st = 0; st < 2; st++)
        #pragma unroll
        for (int nt = 0; nt < 16; nt++)
            #pragma unroll
            for (int jj = 0; jj < 4; jj++) oacc[st][nt][jj] = 0.0f;
    float lacc[2][4];
    #pragma unroll
    for (int st = 0; st < 2; st++)
        #pragma unroll
        for (int jj = 0; jj < 4; jj++) lacc[st][jj] = 0.0f;

    for (int t = 0; t < 32; t++) {
        const uint32_t kBase = kCommon + (uint32_t)(t & 1) * 32768u;
        const uint32_t vBase = vCommon + (uint32_t)(t & 1) * 32768u;

        CP_WAIT0();
        __syncthreads();   // K(t),V(t) visible; prior reads of reused bufs done

        // Prefetch tile t+1
        if (t + 1 < 32) {
            const int ok = UK0 + ((t + 1) & 1) * 8192;
            const int ov = UV0 + ((t + 1) & 1) * 8192;
            const __half* Kg = g_K + ((size_t)b * SS + (t + 1) * 128) * HH;
            const __half* Vg = g_Vt + (size_t)(b * HH) * SS + (t + 1) * 128;
            #pragma unroll
            for (int i = 0; i < 8; i++) {
                int idx = tid + i * 256;
                int r = idx >> 4;
                int c4 = (idx & 15) << 2;
                int sw = c4 ^ ((r & 7) << 2);
                cp_async16(smem_u32 + (ok + r * 64 + sw) * 4, Kg + r * HH + c4 * 2);
                cp_async16(smem_u32 + (ov + r * 64 + sw) * 4, Vg + (size_t)r * SS + c4 * 2);
            }
            CP_COMMIT();
        }

        // --- S = Q . K^T : m32 x n64 x k128, fp16 ACCUMULATE (full rate) ---
        uint32_t sacc[2][8][2];
        #pragma unroll
        for (int st = 0; st < 2; st++)
            #pragma unroll
            for (int nt = 0; nt < 8; nt++) {
                sacc[st][nt][0] = 0u;
                sacc[st][nt][1] = 0u;
            }

        #pragma unroll
        for (int ks = 0; ks < 8; ks++) {
            const uint32_t col4 = ((uint32_t)(ks * 32)) ^ xhi4;
            uint32_t qa0[4], qa1[4];
            ldsm_x4(qa0, qBase + col4);
            ldsm_x4(qa1, qBase + col4 + 4096);
            #pragma unroll
            for (int nb = 0; nb < 4; nb++) {
                uint32_t bk[4];
                ldsm_x4(bk, kBase + (uint32_t)nb * 4096 + col4);
                mma_f16h(sacc[0][2 * nb],     qa0, bk[0], bk[1]);
                mma_f16h(sacc[1][2 * nb],     qa1, bk[0], bk[1]);
                mma_f16h(sacc[0][2 * nb + 1], qa0, bk[2], bk[3]);
                mma_f16h(sacc[1][2 * nb + 1], qa1, bk[2], bk[3]);
            }
        }

        // --- softmax: f16 C-frag -> ex2.approx.f16x2 directly ---
        uint32_t pf[4][2][4];
        #pragma unroll
        for (int st = 0; st < 2; st++) {
            #pragma unroll
            for (int nt = 0; nt < 8; nt++) {
                pf[nt >> 1][st][(nt & 1) * 2]     = hex2(sacc[st][nt][0]);
                pf[nt >> 1][st][(nt & 1) * 2 + 1] = hex2(sacc[st][nt][1]);
            }
        }

        // --- O += P . V (m32 x h128 x k64) and lsum += P . 1 (f32 acc) ---
        #pragma unroll
        for (int kk = 0; kk < 4; kk++) {
            const uint32_t col4v = (vColOff + (uint32_t)(kk * 32)) ^ xhi4;
            mma_f16(lacc[0], pf[kk][0], ONES_H2, ONES_H2);
            mma_f16(lacc[1], pf[kk][1], ONES_H2, ONES_H2);
            #pragma unroll
            for (int hb = 0; hb < 8; hb++) {
                uint32_t bv[4];
                ldsm_x4(bv, vBase + (uint32_t)hb * 4096 + col4v);
                mma_f16(oacc[0][2 * hb],     pf[kk][0], bv[0], bv[1]);
                mma_f16(oacc[1][2 * hb],     pf[kk][1], bv[0], bv[1]);
                mma_f16(oacc[0][2 * hb + 1], pf[kk][0], bv[2], bv[3]);
                mma_f16(oacc[1][2 * hb + 1], pf[kk][1], bv[2], bv[3]);
            }
        }
    }

    // --- Balanced combine, COMPILE-TIME indices: each warp publishes the 64
    //     cols of the OPPOSITE kh + its lsum. Branch on kh keeps nt constant.
    __syncthreads();   // staging done with smem; safe to reuse
    {
        float* Ocmb = (float*)smu;                 // 4 strips x 32 x 128 f32
        float* Obase = Ocmb + (m0 >> 5) * 4096;
        if (kh == 0) {
            float* LSme = (float*)(smu + ULS0);
            #pragma unroll
            for (int st = 0; st < 2; st++) {
                int r0 = 16 * st + g;
                int r1 = r0 + 8;
                if (tg == 0) { LSme[m0 + r0] = lacc[st][0]; LSme[m0 + r1] = lacc[st][2]; }
                #pragma unroll
                for (int nto = 0; nto < 8; nto++) {
                    int col = (8 + nto) * 8 + 2 * tg;   // publish cols 64..127
                    *(float2*)(Obase + r0 * 128 + col) =
                        make_float2(oacc[st][8 + nto][0], oacc[st][8 + nto][1]);
                    *(float2*)(Obase + r1 * 128 + col) =
                        make_float2(oacc[st][8 + nto][2], oacc[st][8 + nto][3]);
                }
            }
        } else {
            float* LSme = (float*)(smu + ULS1);
            #pragma unroll
            for (int st = 0; st < 2; st++) {
                int r0 = 16 * st + g;
                int r1 = r0 + 8;
                if (tg == 0) { LSme[m0 + r0] = lacc[st][0]; LSme[m0 + r1] = lacc[st][2]; }
                #pragma unroll
                for (int nto = 0; nto < 8; nto++) {
                    int col = nto * 8 + 2 * tg;         // publish cols 0..63
                    *(float2*)(Obase + r0 * 128 + col) =
                        make_float2(oacc[st][nto][0], oacc[st][nto][1]);
                    *(float2*)(Obase + r1 * 128 + col) =
                        make_float2(oacc[st][nto][2], oacc[st][nto][3]);
                }
            }
        }
    }
    __syncthreads();

    // --- epilogue: each warp combines + writes its OWN 64 cols ---
    {
        const float* Ocmb = (const float*)smu + (m0 >> 5) * 4096;
        float* og = out + ((size_t)(b * SS) + q0) * HH;
        if (kh == 0) {
            const float* LSo = (const float*)(smu + ULS1);
            #pragma unroll
            for (int st = 0; st < 2; st++) {
                int r0 = 16 * st + g;
                int r1 = r0 + 8;
                float inv0 = 1.0f / (lacc[st][0] + LSo[m0 + r0]);
                float inv1 = 1.0f / (lacc[st][2] + LSo[m0 + r1]);
                float* o0 = og + (size_t)(m0 + r0) * HH;
                float* o1 = og + (size_t)(m0 + r1) * HH;
                #pragma unroll
                for (int nto = 0; nto < 8; nto++) {
                    int col = nto * 8 + 2 * tg;         // own cols 0..63
                    float2 p0 = *(const float2*)(Ocmb + r0 * 128 + col);
                    float2 p1 = *(const float2*)(Ocmb + r1 * 128 + col);
                    *(float2*)(o0 + col) =
                        make_float2((oacc[st][nto][0] + p0.x) * inv0,
                                    (oacc[st][nto][1] + p0.y) * inv0);
                    *(float2*)(o1 + col) =
                        make_float2((oacc[st][nto][2] + p1.x) * inv1,
                                    (oacc[st][nto][3] + p1.y) * inv1);
                }
            }
        } else {
            const float* LSo = (const float*)(smu + ULS0);
            #pragma unroll
            for (int st = 0; st < 2; st++) {
                int r0 = 16 * st + g;
                int r1 = r0 + 8;
                float inv0 = 1.0f / (lacc[st][0] + LSo[m0 + r0]);
                float inv1 = 1.0f / (lacc[st][2] + LSo[m0 + r1]);
                float* o0 = og + (size_t)(m0 + r0) * HH;
                float* o1 = og + (size_t)(m0 + r1) * HH;
                #pragma unroll
                for (int nto = 0; nto < 8; nto++) {
                    int col = (8 + nto) * 8 + 2 * tg;   // own cols 64..127
                    float2 p0 = *(const float2*)(Ocmb + r0 * 128 + col);
                    float2 p1 = *(const float2*)(Ocmb + r1 * 128 + col);
                    *(float2*)(o0 + col) =
                        make_float2((oacc[st][8 + nto][0] + p0.x) * inv0,
                                    (oacc[st][8 + nto][1] + p0.y) * inv0);
                    *(float2*)(o1 + col) =
                        make_float2((oacc[st][8 + nto][2] + p1.x) * inv1,
                                    (oacc[st][8 + nto][3] + p1.y) * inv1);
                }
            }
        }
    }
}

// ---------------------------------------------------------------------------
extern "C" void kernel_launch(void* const* d_in, const int* in_sizes, int n_in,
                              void* d_out, int out_size)
{
    const float* X    = (const float*)d_in[0];   // [4,4096,128]
    const float* W    = (const float*)d_in[1];   // [384,128]
    const float* bias = (const float*)d_in[2];   // [384]
    float* out = (float*)d_out;                  // [4,4096,128]

    cudaFuncSetAttribute(qkv_f16, cudaFuncAttributeMaxDynamicSharedMemorySize, SMEM_QKV);
    cudaFuncSetAttribute(attn_kernel, cudaFuncAttributeMaxDynamicSharedMemorySize, SMEM_ATTN);

    qkv_f16<<<128, 256, SMEM_QKV>>>(X, W, bias);
    attn_kernel<<<dim3(SS / 128, BB), 256, SMEM_ATTN>>>(out);
}